// round 15
// baseline (speedup 1.0000x reference)
#include <cuda_runtime.h>
#include <cuda_bf16.h>
#include <cstdint>

// ---------------------------------------------------------------------------
// Problem constants
// ---------------------------------------------------------------------------
#define BB   16
#define TT   512
#define DD   512          // UNITS
#define GG   2048         // 4*UNITS
#define QKVD 64
#define NH   8
#define HD   8
#define EPS  1e-6f

#define NROW (BB * TT)    // 8192 rows

// ---------------------------------------------------------------------------
// Scratch: device globals (no allocation allowed)
// ---------------------------------------------------------------------------
__device__ float g_xg  [NROW * GG];      // 64 MB  x@Wx + b
__device__ float g_hseq[NROW * DD];      // 16 MB  LSTM hidden sequence
__device__ float g_hp  [NROW * DD];      // 16 MB  LN1(h) + x   (skip2)
__device__ float g_q   [NROW * QKVD];
__device__ float g_k   [NROW * QKVD];
__device__ float g_v   [NROW * QKVD];
__device__ float g_ctx [NROW * QKVD];
__device__ float g_ao  [NROW * DD];      // attn out
__device__ float g_gate[NROW * DD];      // sigmoid(hp@Wg+bg)
__device__ float g_hbuf[2][BB * DD];     // ping-pong h_t broadcast

// tree-barrier state: 16 group counters (128B apart) + root + generation
__device__ unsigned          g_grp[16 * 32];
__device__ unsigned          g_root = 0;
__device__ volatile unsigned g_bargen = 0;

__device__ __forceinline__ float sigm(float x)  { return 1.f / (1.f + __expf(-x)); }
__device__ __forceinline__ float tfast(float x) { return 2.f * sigm(2.f * x) - 1.f; }

// ---------------------------------------------------------------------------
// TF32 helpers
// ---------------------------------------------------------------------------
__device__ __forceinline__ uint32_t f2tf32(float x) {
    uint32_t r;
    asm("cvt.rna.tf32.f32 %0, %1;" : "=r"(r) : "f"(x));
    return r;
}
__device__ __forceinline__ void mma_tf32(float* c, const uint32_t* a,
                                         const uint32_t* b) {
    asm volatile(
        "mma.sync.aligned.m16n8k8.row.col.f32.tf32.tf32.f32 "
        "{%0,%1,%2,%3}, {%4,%5,%6,%7}, {%8,%9}, {%0,%1,%2,%3};"
        : "+f"(c[0]), "+f"(c[1]), "+f"(c[2]), "+f"(c[3])
        : "r"(a[0]), "r"(a[1]), "r"(a[2]), "r"(a[3]),
          "r"(b[0]), "r"(b[1]));
}

// ---------------------------------------------------------------------------
// 3xTF32 tensor-core GEMM (R9-proven): C = A@B + bias (ACT=1 sigmoid).
// ---------------------------------------------------------------------------
#define TFP 136    // smem row stride (conflict-free fragment loads)

template<int ACT>
__global__ void __launch_bounds__(256)
gemm_tf32_kernel(const float* __restrict__ A, const float* __restrict__ B,
                 const float* __restrict__ bias, float* __restrict__ C,
                 int K, int N)
{
    __shared__ uint32_t AsH[16][TFP], AsL[16][TFP];
    __shared__ uint32_t BsH[16][TFP], BsL[16][TFP];

    const int tid  = threadIdx.x;
    const int lane = tid & 31;
    const int wid  = tid >> 5;
    const int row0 = blockIdx.y * 128;
    const int col0 = blockIdx.x * 128;
    const int wm   = (wid & 1) * 64;
    const int wn   = (wid >> 1) * 32;
    const int lq   = lane >> 2;
    const int lr   = lane & 3;

    float4 ra[2], rb[2];
#pragma unroll
    for (int u = 0; u < 2; u++) {
        int fa = tid + 256 * u;
        ra[u] = *(const float4*)&A[(size_t)(row0 + (fa >> 2)) * K + ((fa & 3) << 2)];
        int fb = tid + 256 * u;
        rb[u] = *(const float4*)&B[(size_t)(fb >> 5) * N + col0 + ((fb & 31) << 2)];
    }

    float acc[4][4][4];
#pragma unroll
    for (int i = 0; i < 4; i++)
#pragma unroll
        for (int j = 0; j < 4; j++)
#pragma unroll
            for (int r = 0; r < 4; r++) acc[i][j][r] = 0.f;

    for (int k0 = 0; k0 < K; k0 += 16) {
#pragma unroll
        for (int u = 0; u < 2; u++) {
            int fa = tid + 256 * u;
            int m  = fa >> 2;
            int kk = (fa & 3) << 2;
            float va[4] = {ra[u].x, ra[u].y, ra[u].z, ra[u].w};
#pragma unroll
            for (int j = 0; j < 4; j++) {
                uint32_t hi = f2tf32(va[j]);
                AsH[kk + j][m] = hi;
                AsL[kk + j][m] = f2tf32(va[j] - __uint_as_float(hi));
            }
            int fb = tid + 256 * u;
            int bk = fb >> 5;
            int n  = (fb & 31) << 2;
            float vb[4] = {rb[u].x, rb[u].y, rb[u].z, rb[u].w};
#pragma unroll
            for (int j = 0; j < 4; j++) {
                uint32_t hi = f2tf32(vb[j]);
                BsH[bk][n + j] = hi;
                BsL[bk][n + j] = f2tf32(vb[j] - __uint_as_float(hi));
            }
        }
        __syncthreads();

        if (k0 + 16 < K) {
#pragma unroll
            for (int u = 0; u < 2; u++) {
                int fa = tid + 256 * u;
                ra[u] = *(const float4*)
                    &A[(size_t)(row0 + (fa >> 2)) * K + k0 + 16 + ((fa & 3) << 2)];
                int fb = tid + 256 * u;
                rb[u] = *(const float4*)
                    &B[(size_t)(k0 + 16 + (fb >> 5)) * N + col0 + ((fb & 31) << 2)];
            }
        }

#pragma unroll
        for (int ks = 0; ks < 16; ks += 8) {
            uint32_t aH[4][4], aL[4][4];
#pragma unroll
            for (int mt = 0; mt < 4; mt++) {
                int m = wm + mt * 16 + lq;
                aH[mt][0] = AsH[ks + lr    ][m    ];
                aH[mt][1] = AsH[ks + lr    ][m + 8];
                aH[mt][2] = AsH[ks + lr + 4][m    ];
                aH[mt][3] = AsH[ks + lr + 4][m + 8];
                aL[mt][0] = AsL[ks + lr    ][m    ];
                aL[mt][1] = AsL[ks + lr    ][m + 8];
                aL[mt][2] = AsL[ks + lr + 4][m    ];
                aL[mt][3] = AsL[ks + lr + 4][m + 8];
            }
            uint32_t bH[4][2], bL[4][2];
#pragma unroll
            for (int nt = 0; nt < 4; nt++) {
                int n = wn + nt * 8 + lq;
                bH[nt][0] = BsH[ks + lr    ][n];
                bH[nt][1] = BsH[ks + lr + 4][n];
                bL[nt][0] = BsL[ks + lr    ][n];
                bL[nt][1] = BsL[ks + lr + 4][n];
            }
#pragma unroll
            for (int mt = 0; mt < 4; mt++)
#pragma unroll
                for (int nt = 0; nt < 4; nt++) {
                    mma_tf32(acc[mt][nt], aH[mt], bL[nt]);
                    mma_tf32(acc[mt][nt], aL[mt], bH[nt]);
                    mma_tf32(acc[mt][nt], aH[mt], bH[nt]);
                }
        }
        __syncthreads();
    }

#pragma unroll
    for (int mt = 0; mt < 4; mt++) {
#pragma unroll
        for (int nt = 0; nt < 4; nt++) {
            int m = row0 + wm + mt * 16 + lq;
            int n = col0 + wn + nt * 8 + 2 * lr;
            float b0 = bias[n], b1 = bias[n + 1];
            float v0 = acc[mt][nt][0] + b0;
            float v1 = acc[mt][nt][1] + b1;
            float v2 = acc[mt][nt][2] + b0;
            float v3 = acc[mt][nt][3] + b1;
            if (ACT) { v0 = sigm(v0); v1 = sigm(v1); v2 = sigm(v2); v3 = sigm(v3); }
            *(float2*)&C[(size_t)m * N + n]       = make_float2(v0, v1);
            *(float2*)&C[(size_t)(m + 8) * N + n] = make_float2(v2, v3);
        }
    }
}

// ---------------------------------------------------------------------------
// Scalar GEMM core (proven): used for the small GEMMs (qkv, Wo).
// ---------------------------------------------------------------------------
template<int BM, int BN, int BK, int TM, int TN, int ACT>
__device__ __forceinline__ void
gemm_core(const float* __restrict__ A, const float* __restrict__ B,
          const float* __restrict__ bias, float* __restrict__ C,
          int K, int N, int row0, int col0)
{
    __shared__ float As[BK][BM + 4];
    __shared__ float Bs[BK][BN];

    constexpr int NA = BM * BK / 1024;
    constexpr int NB = BK * BN / 1024;
    constexpr int TX = BN / TN;

    const int tid = threadIdx.x;
    const int tx  = tid % TX;
    const int ty  = tid / TX;

    float4 ra[NA], rb[NB];

#pragma unroll
    for (int u = 0; u < NA; u++) {
        int fa = tid + 256 * u;
        int m  = fa / (BK / 4);
        int kk = (fa % (BK / 4)) * 4;
        ra[u] = *(const float4*)&A[(size_t)(row0 + m) * K + kk];
    }
#pragma unroll
    for (int u = 0; u < NB; u++) {
        int fb = tid + 256 * u;
        int kk = fb / (BN / 4);
        int n  = (fb % (BN / 4)) * 4;
        rb[u] = *(const float4*)&B[(size_t)kk * N + col0 + n];
    }

    float acc[TM][TN];
#pragma unroll
    for (int i = 0; i < TM; i++)
#pragma unroll
        for (int j = 0; j < TN; j++) acc[i][j] = 0.f;

    for (int k0 = 0; k0 < K; k0 += BK) {
#pragma unroll
        for (int u = 0; u < NA; u++) {
            int fa = tid + 256 * u;
            int m  = fa / (BK / 4);
            int kk = (fa % (BK / 4)) * 4;
            As[kk + 0][m] = ra[u].x;
            As[kk + 1][m] = ra[u].y;
            As[kk + 2][m] = ra[u].z;
            As[kk + 3][m] = ra[u].w;
        }
#pragma unroll
        for (int u = 0; u < NB; u++) {
            int fb = tid + 256 * u;
            int kk = fb / (BN / 4);
            int n  = (fb % (BN / 4)) * 4;
            *(float4*)&Bs[kk][n] = rb[u];
        }
        __syncthreads();

        if (k0 + BK < K) {
#pragma unroll
            for (int u = 0; u < NA; u++) {
                int fa = tid + 256 * u;
                int m  = fa / (BK / 4);
                int kk = (fa % (BK / 4)) * 4;
                ra[u] = *(const float4*)&A[(size_t)(row0 + m) * K + k0 + BK + kk];
            }
#pragma unroll
            for (int u = 0; u < NB; u++) {
                int fb = tid + 256 * u;
                int kk = fb / (BN / 4);
                int n  = (fb % (BN / 4)) * 4;
                rb[u] = *(const float4*)&B[(size_t)(k0 + BK + kk) * N + col0 + n];
            }
        }

#pragma unroll
        for (int kk = 0; kk < BK; kk++) {
            float av[TM], bv[TN];
#pragma unroll
            for (int i = 0; i < TM; i += 4) {
                float4 t = *(const float4*)&As[kk][ty * TM + i];
                av[i] = t.x; av[i + 1] = t.y; av[i + 2] = t.z; av[i + 3] = t.w;
            }
#pragma unroll
            for (int j = 0; j < TN; j += 4) {
                float4 t = *(const float4*)&Bs[kk][tx * TN + j];
                bv[j] = t.x; bv[j + 1] = t.y; bv[j + 2] = t.z; bv[j + 3] = t.w;
            }
#pragma unroll
            for (int i = 0; i < TM; i++)
#pragma unroll
                for (int j = 0; j < TN; j++)
                    acc[i][j] += av[i] * bv[j];
        }
        __syncthreads();
    }

#pragma unroll
    for (int i = 0; i < TM; i++) {
        float* crow = &C[(size_t)(row0 + ty * TM + i) * N + col0 + tx * TN];
#pragma unroll
        for (int j = 0; j < TN; j += 4) {
            float4 o;
            o.x = acc[i][j + 0] + bias[col0 + tx * TN + j + 0];
            o.y = acc[i][j + 1] + bias[col0 + tx * TN + j + 1];
            o.z = acc[i][j + 2] + bias[col0 + tx * TN + j + 2];
            o.w = acc[i][j + 3] + bias[col0 + tx * TN + j + 3];
            if (ACT) {
                o.x = sigm(o.x); o.y = sigm(o.y);
                o.z = sigm(o.z); o.w = sigm(o.w);
            }
            *(float4*)&crow[j] = o;
        }
    }
}

template<int BM, int BN, int BK, int TM, int TN, int ACT>
__global__ void __launch_bounds__(256)
gemm2_kernel(const float* __restrict__ A, const float* __restrict__ B,
             const float* __restrict__ bias, float* __restrict__ C,
             int K, int N)
{
    gemm_core<BM, BN, BK, TM, TN, ACT>(A, B, bias, C, K, N,
                                       blockIdx.y * BM, blockIdx.x * BN);
}

// Fused q/k/v projections: blockIdx.z selects (W, bias, out).
__global__ void __launch_bounds__(256)
qkv_kernel(const float* __restrict__ hp,
           const float* __restrict__ Wq, const float* __restrict__ bq,
           const float* __restrict__ Wk, const float* __restrict__ bk,
           const float* __restrict__ Wv, const float* __restrict__ bv,
           float* __restrict__ q, float* __restrict__ k, float* __restrict__ v)
{
    const float* W; const float* bi; float* C;
    if (blockIdx.z == 0)      { W = Wq; bi = bq; C = q; }
    else if (blockIdx.z == 1) { W = Wk; bi = bk; C = k; }
    else                      { W = Wv; bi = bv; C = v; }
    gemm_core<64, 64, 16, 4, 4, 0>(hp, W, bi, C, DD, QKVD,
                                   blockIdx.y * 64, blockIdx.x * 64);
}

// ---------------------------------------------------------------------------
// Reset tree-barrier counters (runs before lstm_kernel each replay; the
// kernel boundary provides the sync, so there is no launch-time race).
// ---------------------------------------------------------------------------
__global__ void lstm_reset_kernel()
{
    for (int i = threadIdx.x; i < 16 * 32; i += blockDim.x)
        g_grp[i] = 0u;
    if (threadIdx.x == 0) {
        g_root   = 0u;
        g_bargen = 0u;
    }
}

// ---------------------------------------------------------------------------
// Persistent LSTM recurrence. 128 CTAs x 256 threads; CTA c owns hidden
// units 4c..4c+3. Grid barrier = two-level atomic tree (proven primitives:
// fence + atomicAdd + volatile spin), monotonic counters (no resets mid-run):
//   group counters: 16 x (8 CTAs each, 128B apart) -> root (16 arrivals)
//   last root arrival publishes generation t+1; everyone spins on it.
// ---------------------------------------------------------------------------
__global__ void __launch_bounds__(256, 1)
lstm_kernel(const float* __restrict__ xg, const float* __restrict__ Wh)
{
    __shared__ __align__(16) float h_s[BB * DD];   // 32 KB  h_{t-1}
    __shared__ float red[8 * 16][17];              // padded: no bank conflicts

    const int tid  = threadIdx.x;
    const int lane = tid & 31;
    const int wid  = tid >> 5;
    const int u0   = blockIdx.x * 4;

    const int dc   = tid >> 4;
    const int jp   = tid & 15;
    const int colp = ((jp >> 2) * DD) + u0 + (jp & 3);

    const int gb = tid & 15;
    const int gu = tid >> 4;

    unsigned* grpcnt = &g_grp[(blockIdx.x >> 3) << 5];   // this CTA's group

    float w[32];
#pragma unroll
    for (int i = 0; i < 32; i++)
        w[i] = Wh[(size_t)(dc * 32 + i) * GG + colp];

    float c_reg = 0.f;

    for (int t = 0; t < TT; t++) {
        float xr0, xr1, xr2, xr3;
        if (tid < 64) {
            const float* xp = &xg[((size_t)(gb * TT) + t) * GG + u0 + gu];
            xr0 = xp[0 * DD]; xr1 = xp[1 * DD];
            xr2 = xp[2 * DD]; xr3 = xp[3 * DD];
        }

        if (t > 0) {
            const float4* src = (const float4*)(g_hbuf[(t + 1) & 1]);
            float4* dst = (float4*)h_s;
#pragma unroll
            for (int i = 0; i < 8; i++)
                dst[tid + 256 * i] = __ldcg(&src[tid + 256 * i]);
        }
        __syncthreads();

        if (t > 0) {
#pragma unroll 4
            for (int b = 0; b < BB; b++) {
                const float4* hr = (const float4*)&h_s[b * DD + dc * 32];
                float p = 0.f;
#pragma unroll
                for (int i = 0; i < 8; i++) {
                    float4 hv = hr[i];
                    p += hv.x * w[4 * i + 0];
                    p += hv.y * w[4 * i + 1];
                    p += hv.z * w[4 * i + 2];
                    p += hv.w * w[4 * i + 3];
                }
                p += __shfl_down_sync(0xffffffffu, p, 16);
                if (lane < 16) red[wid * 16 + lane][b] = p;
            }
        }
        __syncthreads();

        if (tid < 64) {
            float ga[4] = {xr0, xr1, xr2, xr3};
            if (t > 0) {
#pragma unroll
                for (int g = 0; g < 4; g++) {
                    const int jj = g * 4 + gu;
                    float s = 0.f;
#pragma unroll
                    for (int wq = 0; wq < 8; wq++)
                        s += red[wq * 16 + jj][gb];
                    ga[g] += s;
                }
            }
            float i_ = sigm(ga[0]);
            float f_ = sigm(ga[1]);
            float o_ = sigm(ga[3]);
            float cg = tfast(ga[2]);
            c_reg = f_ * c_reg + i_ * cg;
            float h = o_ * tfast(c_reg);
            __stcg(&g_hbuf[t & 1][gb * DD + u0 + gu], h);
            g_hseq[((size_t)(gb * TT) + t) * DD + u0 + gu] = h;
        }
        __syncthreads();

        // ---- two-level atomic tree barrier (monotonic counters) ----
        if (tid == 0) {
            __threadfence();                       // release this CTA's writes
            const unsigned tgt = (unsigned)(t + 1);
            if (atomicAdd(grpcnt, 1u) == 8u * tgt - 1u) {      // last in group
                if (atomicAdd(&g_root, 1u) == 16u * tgt - 1u) {// last group
                    __threadfence();
                    g_bargen = tgt;                // publish generation
                }
            }
            while (g_bargen < tgt) { }             // volatile spin
            __threadfence();                       // acquire
        }
        __syncthreads();
    }
}

// ---------------------------------------------------------------------------
// LN1 + residual: out = LN(hin)*sc + bi + res      (one block per row)
// ---------------------------------------------------------------------------
__global__ void __launch_bounds__(256)
ln_add_kernel(const float* __restrict__ hin, const float* __restrict__ res,
              const float* __restrict__ sc, const float* __restrict__ bi,
              float* __restrict__ out)
{
    __shared__ float ws[8], wq[8];
    const int row = blockIdx.x;
    const int tid = threadIdx.x;

    float2 v = ((const float2*)(hin + (size_t)row * DD))[tid];
    float s = v.x + v.y;
    float q = v.x * v.x + v.y * v.y;
#pragma unroll
    for (int o = 16; o; o >>= 1) {
        s += __shfl_xor_sync(~0u, s, o);
        q += __shfl_xor_sync(~0u, q, o);
    }
    if ((tid & 31) == 0) { ws[tid >> 5] = s; wq[tid >> 5] = q; }
    __syncthreads();
    if (tid < 32) {
        float s2 = (tid < 8) ? ws[tid] : 0.f;
        float q2 = (tid < 8) ? wq[tid] : 0.f;
#pragma unroll
        for (int o = 4; o; o >>= 1) {
            s2 += __shfl_xor_sync(~0u, s2, o);
            q2 += __shfl_xor_sync(~0u, q2, o);
        }
        if (tid == 0) { ws[0] = s2; wq[0] = q2; }
    }
    __syncthreads();
    float mean = ws[0] * (1.f / (float)DD);
    float var  = wq[0] * (1.f / (float)DD) - mean * mean;
    float inv  = rsqrtf(var + EPS);

    float2 r  = ((const float2*)(res + (size_t)row * DD))[tid];
    float2 sv = ((const float2*)sc)[tid];
    float2 bv = ((const float2*)bi)[tid];
    float2 o2;
    o2.x = (v.x - mean) * inv * sv.x + bv.x + r.x;
    o2.y = (v.y - mean) * inv * sv.y + bv.y + r.y;
    ((float2*)(out + (size_t)row * DD))[tid] = o2;
}

// ---------------------------------------------------------------------------
// Final: out = LN(ao*gate + hp)*sc + bi            (one block per row)
// ---------------------------------------------------------------------------
__global__ void __launch_bounds__(256)
final_kernel(const float* __restrict__ ao, const float* __restrict__ gate,
             const float* __restrict__ hp, const float* __restrict__ sc,
             const float* __restrict__ bi, float* __restrict__ out)
{
    __shared__ float ws[8], wq[8];
    const int row = blockIdx.x;
    const int tid = threadIdx.x;

    float2 a = ((const float2*)(ao   + (size_t)row * DD))[tid];
    float2 g = ((const float2*)(gate + (size_t)row * DD))[tid];
    float2 h = ((const float2*)(hp   + (size_t)row * DD))[tid];
    float2 v;
    v.x = a.x * g.x + h.x;
    v.y = a.y * g.y + h.y;

    float s = v.x + v.y;
    float q = v.x * v.x + v.y * v.y;
#pragma unroll
    for (int o = 16; o; o >>= 1) {
        s += __shfl_xor_sync(~0u, s, o);
        q += __shfl_xor_sync(~0u, q, o);
    }
    if ((tid & 31) == 0) { ws[tid >> 5] = s; wq[tid >> 5] = q; }
    __syncthreads();
    if (tid < 32) {
        float s2 = (tid < 8) ? ws[tid] : 0.f;
        float q2 = (tid < 8) ? wq[tid] : 0.f;
#pragma unroll
        for (int o = 4; o; o >>= 1) {
            s2 += __shfl_xor_sync(~0u, s2, o);
            q2 += __shfl_xor_sync(~0u, q2, o);
        }
        if (tid == 0) { ws[0] = s2; wq[0] = q2; }
    }
    __syncthreads();
    float mean = ws[0] * (1.f / (float)DD);
    float var  = wq[0] * (1.f / (float)DD) - mean * mean;
    float inv  = rsqrtf(var + EPS);

    float2 sv = ((const float2*)sc)[tid];
    float2 bv = ((const float2*)bi)[tid];
    float2 o2;
    o2.x = (v.x - mean) * inv * sv.x + bv.x;
    o2.y = (v.y - mean) * inv * sv.y + bv.y;
    ((float2*)(out + (size_t)row * DD))[tid] = o2;
}

// ---------------------------------------------------------------------------
// Attention: grid (b=16, h=8, quarter=4), 256 threads.
// ---------------------------------------------------------------------------
__global__ void __launch_bounds__(256)
attn_kernel(const float* __restrict__ q, const float* __restrict__ k,
            const float* __restrict__ v, float* __restrict__ ctx)
{
    __shared__ float Kt[HD][TT];   // 16 KB
    __shared__ float Vt[HD][TT];   // 16 KB

    const int b    = blockIdx.x;
    const int hh   = blockIdx.y;
    const int tid  = threadIdx.x;
    const int lane = tid & 31;
    const int wid  = tid >> 5;
    const float scale = 0.35355339059327373f;   // 1/sqrt(8)

    for (int idx = tid; idx < TT * HD; idx += 256) {
        int s = idx >> 3, d = idx & 7;
        size_t off = ((size_t)(b * TT) + s) * QKVD + hh * HD + d;
        Kt[d][s] = k[off];
        Vt[d][s] = v[off];
    }
    __syncthreads();

    const int row0 = blockIdx.z * 128 + wid * 16;
    for (int r = 0; r < 16; r++) {
        const int qrow = row0 + r;
        const float* qp = &q[((size_t)(b * TT) + qrow) * QKVD + hh * HD];
        float4 q0 = *(const float4*)qp;
        float4 q1 = *(const float4*)(qp + 4);
        float qv[8];
        qv[0] = q0.x * scale; qv[1] = q0.y * scale;
        qv[2] = q0.z * scale; qv[3] = q0.w * scale;
        qv[4] = q1.x * scale; qv[5] = q1.y * scale;
        qv[6] = q1.z * scale; qv[7] = q1.w * scale;

        float sc[16];
#pragma unroll
        for (int kk = 0; kk < 16; kk++) {
            int s = kk * 32 + lane;
            float acc = 0.f;
#pragma unroll
            for (int d = 0; d < 8; d++) acc += qv[d] * Kt[d][s];
            sc[kk] = acc;
        }
        float m = sc[0];
#pragma unroll
        for (int kk = 1; kk < 16; kk++) m = fmaxf(m, sc[kk]);
#pragma unroll
        for (int o = 16; o; o >>= 1)
            m = fmaxf(m, __shfl_xor_sync(~0u, m, o));
        float sum = 0.f;
#pragma unroll
        for (int kk = 0; kk < 16; kk++) {
            sc[kk] = __expf(sc[kk] - m);
            sum += sc[kk];
        }
#pragma unroll
        for (int o = 16; o; o >>= 1)
            sum += __shfl_xor_sync(~0u, sum, o);

        float acc[8];
#pragma unroll
        for (int d = 0; d < 8; d++) acc[d] = 0.f;
#pragma unroll
        for (int kk = 0; kk < 16; kk++) {
            int s = kk * 32 + lane;
            float wgt = sc[kk];
#pragma unroll
            for (int d = 0; d < 8; d++) acc[d] += wgt * Vt[d][s];
        }
#pragma unroll
        for (int d = 0; d < 8; d++)
#pragma unroll
            for (int o = 16; o; o >>= 1)
                acc[d] += __shfl_xor_sync(~0u, acc[d], o);

        if (lane == 0) {
            float invs = 1.f / sum;
            float* op = &ctx[((size_t)(b * TT) + qrow) * QKVD + hh * HD];
            float4 o0 = {acc[0] * invs, acc[1] * invs, acc[2] * invs, acc[3] * invs};
            float4 o1 = {acc[4] * invs, acc[5] * invs, acc[6] * invs, acc[7] * invs};
            *(float4*)op       = o0;
            *(float4*)(op + 4) = o1;
        }
    }
}

// ---------------------------------------------------------------------------
// Launch
// ---------------------------------------------------------------------------
extern "C" void kernel_launch(void* const* d_in, const int* in_sizes, int n_in,
                              void* d_out, int out_size)
{
    (void)in_sizes; (void)n_in; (void)out_size;

    const float* x   = (const float*)d_in[0];
    const float* Wx  = (const float*)d_in[1];
    const float* Wh  = (const float*)d_in[2];
    const float* b   = (const float*)d_in[3];
    const float* l1s = (const float*)d_in[4];
    const float* l1b = (const float*)d_in[5];
    const float* Wq  = (const float*)d_in[6];
    const float* bq  = (const float*)d_in[7];
    const float* Wk  = (const float*)d_in[8];
    const float* bk  = (const float*)d_in[9];
    const float* Wv  = (const float*)d_in[10];
    const float* bv  = (const float*)d_in[11];
    const float* Wo  = (const float*)d_in[12];
    const float* bo  = (const float*)d_in[13];
    const float* Wg  = (const float*)d_in[14];
    const float* bg  = (const float*)d_in[15];
    const float* l2s = (const float*)d_in[16];
    const float* l2b = (const float*)d_in[17];
    float* out = (float*)d_out;

    float *xg, *hseq, *hp, *qb, *kb, *vb, *ctx, *ao, *gate;
    cudaGetSymbolAddress((void**)&xg,   g_xg);
    cudaGetSymbolAddress((void**)&hseq, g_hseq);
    cudaGetSymbolAddress((void**)&hp,   g_hp);
    cudaGetSymbolAddress((void**)&qb,   g_q);
    cudaGetSymbolAddress((void**)&kb,   g_k);
    cudaGetSymbolAddress((void**)&vb,   g_v);
    cudaGetSymbolAddress((void**)&ctx,  g_ctx);
    cudaGetSymbolAddress((void**)&ao,   g_ao);
    cudaGetSymbolAddress((void**)&gate, g_gate);

    // 0. reset tree-barrier counters (kernel boundary = safe reset per replay)
    lstm_reset_kernel<<<1, 256>>>();

    // 1. xg = x @ Wx + b    [8192,2048] = [8192,512]@[512,2048]  (3xTF32 MMA)
    gemm_tf32_kernel<0><<<dim3(GG / 128, NROW / 128), 256>>>(x, Wx, b, xg, DD, GG);

    // 2. LSTM recurrence (persistent, tree grid barrier)
    lstm_kernel<<<128, 256>>>(xg, Wh);

    // 3. hp = LN1(hseq) + x
    ln_add_kernel<<<NROW, 256>>>(hseq, x, l1s, l1b, hp);

    // 4. fused q,k,v projections   [8192,64] = [8192,512]@[512,64]
    qkv_kernel<<<dim3(1, NROW / 64, 3), 256>>>(
        hp, Wq, bq, Wk, bk, Wv, bv, qb, kb, vb);

    // 5. attention -> ctx
    attn_kernel<<<dim3(BB, NH, 4), 256>>>(qb, kb, vb, ctx);

    // 6. attn_out = ctx @ Wo + bo     [8192,512] = [8192,64]@[64,512]
    gemm2_kernel<128, 128, 16, 8, 8, 0><<<dim3(DD / 128, NROW / 128), 256>>>(
        ctx, Wo, bo, ao, QKVD, DD);

    // 7. gate = sigmoid(hp @ Wg + bg) [8192,512] = [8192,512]@[512,512]  (3xTF32)
    gemm_tf32_kernel<1><<<dim3(DD / 128, NROW / 128), 256>>>(hp, Wg, bg, gate, DD, DD);

    // 8. out = LN2(ao*gate + hp)
    final_kernel<<<NROW, 256>>>(ao, gate, hp, l2s, l2b, out);
}

// round 17
// speedup vs baseline: 1.2275x; 1.2275x over previous
#include <cuda_runtime.h>
#include <cuda_bf16.h>
#include <cstdint>

// ---------------------------------------------------------------------------
// Problem constants
// ---------------------------------------------------------------------------
#define BB   16
#define TT   512
#define DD   512          // UNITS
#define GG   2048         // 4*UNITS
#define QKVD 64
#define NH   8
#define HD   8
#define EPS  1e-6f

#define NROW (BB * TT)    // 8192 rows
#define HSP  520          // padded h_s row stride (bank-conflict reduction)

// ---------------------------------------------------------------------------
// Scratch: device globals (no allocation allowed)
// ---------------------------------------------------------------------------
__device__ float g_xg  [NROW * GG];      // 64 MB  x@Wx + b
__device__ float g_hseq[NROW * DD];      // 16 MB  LSTM hidden sequence
__device__ float g_hp  [NROW * DD];      // 16 MB  LN1(h) + x   (skip2)
__device__ float g_q   [NROW * QKVD];
__device__ float g_k   [NROW * QKVD];
__device__ float g_v   [NROW * QKVD];
__device__ float g_ctx [NROW * QKVD];
__device__ float g_ao  [NROW * DD];      // attn out
__device__ float g_gate[NROW * DD];      // sigmoid(hp@Wg+bg)
__device__ float g_hbuf[2][BB * DD];     // ping-pong h_t broadcast
__device__ unsigned          g_barcount = 0;
__device__ volatile unsigned g_bargen   = 0;

__device__ __forceinline__ float sigm(float x)  { return 1.f / (1.f + __expf(-x)); }
__device__ __forceinline__ float tfast(float x) { return 2.f * sigm(2.f * x) - 1.f; }

// ---------------------------------------------------------------------------
// TF32 helpers
// ---------------------------------------------------------------------------
__device__ __forceinline__ uint32_t f2tf32(float x) {
    uint32_t r;
    asm("cvt.rna.tf32.f32 %0, %1;" : "=r"(r) : "f"(x));
    return r;
}
__device__ __forceinline__ void mma_tf32(float* c, const uint32_t* a,
                                         const uint32_t* b) {
    asm volatile(
        "mma.sync.aligned.m16n8k8.row.col.f32.tf32.tf32.f32 "
        "{%0,%1,%2,%3}, {%4,%5,%6,%7}, {%8,%9}, {%0,%1,%2,%3};"
        : "+f"(c[0]), "+f"(c[1]), "+f"(c[2]), "+f"(c[3])
        : "r"(a[0]), "r"(a[1]), "r"(a[2]), "r"(a[3]),
          "r"(b[0]), "r"(b[1]));
}

// ---------------------------------------------------------------------------
// 3xTF32 tensor-core GEMM (R9-proven): C = A@B + bias (ACT=1 sigmoid).
// ---------------------------------------------------------------------------
#define TFP 136    // smem row stride (conflict-free fragment loads)

template<int ACT>
__global__ void __launch_bounds__(256)
gemm_tf32_kernel(const float* __restrict__ A, const float* __restrict__ B,
                 const float* __restrict__ bias, float* __restrict__ C,
                 int K, int N)
{
    __shared__ uint32_t AsH[16][TFP], AsL[16][TFP];
    __shared__ uint32_t BsH[16][TFP], BsL[16][TFP];

    const int tid  = threadIdx.x;
    const int lane = tid & 31;
    const int wid  = tid >> 5;
    const int row0 = blockIdx.y * 128;
    const int col0 = blockIdx.x * 128;
    const int wm   = (wid & 1) * 64;
    const int wn   = (wid >> 1) * 32;
    const int lq   = lane >> 2;
    const int lr   = lane & 3;

    float4 ra[2], rb[2];
#pragma unroll
    for (int u = 0; u < 2; u++) {
        int fa = tid + 256 * u;
        ra[u] = *(const float4*)&A[(size_t)(row0 + (fa >> 2)) * K + ((fa & 3) << 2)];
        int fb = tid + 256 * u;
        rb[u] = *(const float4*)&B[(size_t)(fb >> 5) * N + col0 + ((fb & 31) << 2)];
    }

    float acc[4][4][4];
#pragma unroll
    for (int i = 0; i < 4; i++)
#pragma unroll
        for (int j = 0; j < 4; j++)
#pragma unroll
            for (int r = 0; r < 4; r++) acc[i][j][r] = 0.f;

    for (int k0 = 0; k0 < K; k0 += 16) {
#pragma unroll
        for (int u = 0; u < 2; u++) {
            int fa = tid + 256 * u;
            int m  = fa >> 2;
            int kk = (fa & 3) << 2;
            float va[4] = {ra[u].x, ra[u].y, ra[u].z, ra[u].w};
#pragma unroll
            for (int j = 0; j < 4; j++) {
                uint32_t hi = f2tf32(va[j]);
                AsH[kk + j][m] = hi;
                AsL[kk + j][m] = f2tf32(va[j] - __uint_as_float(hi));
            }
            int fb = tid + 256 * u;
            int bk = fb >> 5;
            int n  = (fb & 31) << 2;
            float vb[4] = {rb[u].x, rb[u].y, rb[u].z, rb[u].w};
#pragma unroll
            for (int j = 0; j < 4; j++) {
                uint32_t hi = f2tf32(vb[j]);
                BsH[bk][n + j] = hi;
                BsL[bk][n + j] = f2tf32(vb[j] - __uint_as_float(hi));
            }
        }
        __syncthreads();

        if (k0 + 16 < K) {
#pragma unroll
            for (int u = 0; u < 2; u++) {
                int fa = tid + 256 * u;
                ra[u] = *(const float4*)
                    &A[(size_t)(row0 + (fa >> 2)) * K + k0 + 16 + ((fa & 3) << 2)];
                int fb = tid + 256 * u;
                rb[u] = *(const float4*)
                    &B[(size_t)(k0 + 16 + (fb >> 5)) * N + col0 + ((fb & 31) << 2)];
            }
        }

#pragma unroll
        for (int ks = 0; ks < 16; ks += 8) {
            uint32_t aH[4][4], aL[4][4];
#pragma unroll
            for (int mt = 0; mt < 4; mt++) {
                int m = wm + mt * 16 + lq;
                aH[mt][0] = AsH[ks + lr    ][m    ];
                aH[mt][1] = AsH[ks + lr    ][m + 8];
                aH[mt][2] = AsH[ks + lr + 4][m    ];
                aH[mt][3] = AsH[ks + lr + 4][m + 8];
                aL[mt][0] = AsL[ks + lr    ][m    ];
                aL[mt][1] = AsL[ks + lr    ][m + 8];
                aL[mt][2] = AsL[ks + lr + 4][m    ];
                aL[mt][3] = AsL[ks + lr + 4][m + 8];
            }
            uint32_t bH[4][2], bL[4][2];
#pragma unroll
            for (int nt = 0; nt < 4; nt++) {
                int n = wn + nt * 8 + lq;
                bH[nt][0] = BsH[ks + lr    ][n];
                bH[nt][1] = BsH[ks + lr + 4][n];
                bL[nt][0] = BsL[ks + lr    ][n];
                bL[nt][1] = BsL[ks + lr + 4][n];
            }
#pragma unroll
            for (int mt = 0; mt < 4; mt++)
#pragma unroll
                for (int nt = 0; nt < 4; nt++) {
                    mma_tf32(acc[mt][nt], aH[mt], bL[nt]);
                    mma_tf32(acc[mt][nt], aL[mt], bH[nt]);
                    mma_tf32(acc[mt][nt], aH[mt], bH[nt]);
                }
        }
        __syncthreads();
    }

#pragma unroll
    for (int mt = 0; mt < 4; mt++) {
#pragma unroll
        for (int nt = 0; nt < 4; nt++) {
            int m = row0 + wm + mt * 16 + lq;
            int n = col0 + wn + nt * 8 + 2 * lr;
            float b0 = bias[n], b1 = bias[n + 1];
            float v0 = acc[mt][nt][0] + b0;
            float v1 = acc[mt][nt][1] + b1;
            float v2 = acc[mt][nt][2] + b0;
            float v3 = acc[mt][nt][3] + b1;
            if (ACT) { v0 = sigm(v0); v1 = sigm(v1); v2 = sigm(v2); v3 = sigm(v3); }
            *(float2*)&C[(size_t)m * N + n]       = make_float2(v0, v1);
            *(float2*)&C[(size_t)(m + 8) * N + n] = make_float2(v2, v3);
        }
    }
}

// ---------------------------------------------------------------------------
// Scalar GEMM core (proven): used for the small GEMMs (qkv, Wo).
// ---------------------------------------------------------------------------
template<int BM, int BN, int BK, int TM, int TN, int ACT>
__device__ __forceinline__ void
gemm_core(const float* __restrict__ A, const float* __restrict__ B,
          const float* __restrict__ bias, float* __restrict__ C,
          int K, int N, int row0, int col0)
{
    __shared__ float As[BK][BM + 4];
    __shared__ float Bs[BK][BN];

    constexpr int NA = BM * BK / 1024;
    constexpr int NB = BK * BN / 1024;
    constexpr int TX = BN / TN;

    const int tid = threadIdx.x;
    const int tx  = tid % TX;
    const int ty  = tid / TX;

    float4 ra[NA], rb[NB];

#pragma unroll
    for (int u = 0; u < NA; u++) {
        int fa = tid + 256 * u;
        int m  = fa / (BK / 4);
        int kk = (fa % (BK / 4)) * 4;
        ra[u] = *(const float4*)&A[(size_t)(row0 + m) * K + kk];
    }
#pragma unroll
    for (int u = 0; u < NB; u++) {
        int fb = tid + 256 * u;
        int kk = fb / (BN / 4);
        int n  = (fb % (BN / 4)) * 4;
        rb[u] = *(const float4*)&B[(size_t)kk * N + col0 + n];
    }

    float acc[TM][TN];
#pragma unroll
    for (int i = 0; i < TM; i++)
#pragma unroll
        for (int j = 0; j < TN; j++) acc[i][j] = 0.f;

    for (int k0 = 0; k0 < K; k0 += BK) {
#pragma unroll
        for (int u = 0; u < NA; u++) {
            int fa = tid + 256 * u;
            int m  = fa / (BK / 4);
            int kk = (fa % (BK / 4)) * 4;
            As[kk + 0][m] = ra[u].x;
            As[kk + 1][m] = ra[u].y;
            As[kk + 2][m] = ra[u].z;
            As[kk + 3][m] = ra[u].w;
        }
#pragma unroll
        for (int u = 0; u < NB; u++) {
            int fb = tid + 256 * u;
            int kk = fb / (BN / 4);
            int n  = (fb % (BN / 4)) * 4;
            *(float4*)&Bs[kk][n] = rb[u];
        }
        __syncthreads();

        if (k0 + BK < K) {
#pragma unroll
            for (int u = 0; u < NA; u++) {
                int fa = tid + 256 * u;
                int m  = fa / (BK / 4);
                int kk = (fa % (BK / 4)) * 4;
                ra[u] = *(const float4*)&A[(size_t)(row0 + m) * K + k0 + BK + kk];
            }
#pragma unroll
            for (int u = 0; u < NB; u++) {
                int fb = tid + 256 * u;
                int kk = fb / (BN / 4);
                int n  = (fb % (BN / 4)) * 4;
                rb[u] = *(const float4*)&B[(size_t)(k0 + BK + kk) * N + col0 + n];
            }
        }

#pragma unroll
        for (int kk = 0; kk < BK; kk++) {
            float av[TM], bv[TN];
#pragma unroll
            for (int i = 0; i < TM; i += 4) {
                float4 t = *(const float4*)&As[kk][ty * TM + i];
                av[i] = t.x; av[i + 1] = t.y; av[i + 2] = t.z; av[i + 3] = t.w;
            }
#pragma unroll
            for (int j = 0; j < TN; j += 4) {
                float4 t = *(const float4*)&Bs[kk][tx * TN + j];
                bv[j] = t.x; bv[j + 1] = t.y; bv[j + 2] = t.z; bv[j + 3] = t.w;
            }
#pragma unroll
            for (int i = 0; i < TM; i++)
#pragma unroll
                for (int j = 0; j < TN; j++)
                    acc[i][j] += av[i] * bv[j];
        }
        __syncthreads();
    }

#pragma unroll
    for (int i = 0; i < TM; i++) {
        float* crow = &C[(size_t)(row0 + ty * TM + i) * N + col0 + tx * TN];
#pragma unroll
        for (int j = 0; j < TN; j += 4) {
            float4 o;
            o.x = acc[i][j + 0] + bias[col0 + tx * TN + j + 0];
            o.y = acc[i][j + 1] + bias[col0 + tx * TN + j + 1];
            o.z = acc[i][j + 2] + bias[col0 + tx * TN + j + 2];
            o.w = acc[i][j + 3] + bias[col0 + tx * TN + j + 3];
            if (ACT) {
                o.x = sigm(o.x); o.y = sigm(o.y);
                o.z = sigm(o.z); o.w = sigm(o.w);
            }
            *(float4*)&crow[j] = o;
        }
    }
}

template<int BM, int BN, int BK, int TM, int TN, int ACT>
__global__ void __launch_bounds__(256)
gemm2_kernel(const float* __restrict__ A, const float* __restrict__ B,
             const float* __restrict__ bias, float* __restrict__ C,
             int K, int N)
{
    gemm_core<BM, BN, BK, TM, TN, ACT>(A, B, bias, C, K, N,
                                       blockIdx.y * BM, blockIdx.x * BN);
}

// Fused q/k/v projections: blockIdx.z selects (W, bias, out).
__global__ void __launch_bounds__(256)
qkv_kernel(const float* __restrict__ hp,
           const float* __restrict__ Wq, const float* __restrict__ bq,
           const float* __restrict__ Wk, const float* __restrict__ bk,
           const float* __restrict__ Wv, const float* __restrict__ bv,
           float* __restrict__ q, float* __restrict__ k, float* __restrict__ v)
{
    const float* W; const float* bi; float* C;
    if (blockIdx.z == 0)      { W = Wq; bi = bq; C = q; }
    else if (blockIdx.z == 1) { W = Wk; bi = bk; C = k; }
    else                      { W = Wv; bi = bv; C = v; }
    gemm_core<64, 64, 16, 4, 4, 0>(hp, W, bi, C, DD, QKVD,
                                   blockIdx.y * 64, blockIdx.x * 64);
}

// ---------------------------------------------------------------------------
// Persistent LSTM recurrence with tensor-core matvec.
// 128 CTAs x 256 threads; CTA c owns 16 gate columns (units 4c..4c+3).
// Warp w owns k-slice [64w, 64w+64); its Wh slice lives in registers as
// 3xTF32 hi/lo m16n8k8 B-fragments (loaded ONCE). Per step each warp does
// 8 k-tiles x (4 LDS + cvt + 6 independent mma chains), partials reduced by
// the proven 64-gate-thread path. Grid barrier = R7/R9-proven single atomic.
// ---------------------------------------------------------------------------
__global__ void __launch_bounds__(256, 1)
lstm_kernel(const float* __restrict__ xg, const float* __restrict__ Wh)
{
    __shared__ __align__(16) float h_s[BB * HSP];  // 33.3 KB padded h_{t-1}
    __shared__ float red[8][16][17];               // warp partials [w][n][b]

    const int tid  = threadIdx.x;
    const int lane = tid & 31;
    const int wid  = tid >> 5;
    const int u0   = blockIdx.x * 4;
    const int lq   = lane >> 2;        // 0..7
    const int lr   = lane & 3;         // 0..3

    // gate-thread identity (valid for tid < 64)
    const int gb = tid & 15;           // batch
    const int gu = tid >> 4;           // unit offset 0..3

    // --- load Wh k-slice into registers as hi/lo tf32 B-fragments (once) ---
    // fragment (nt, kt, s2): element Wh[64w + 8kt + 4 s2 + lr][col(nt*8+lq)]
    uint32_t wbH[2][8][2], wbL[2][8][2];
#pragma unroll
    for (int nt = 0; nt < 2; nt++) {
        const int j   = nt * 8 + lq;
        const int col = ((j >> 2) * DD) + u0 + (j & 3);
#pragma unroll
        for (int kt = 0; kt < 8; kt++) {
#pragma unroll
            for (int s2 = 0; s2 < 2; s2++) {
                int k = 64 * wid + 8 * kt + 4 * s2 + lr;
                float v = Wh[(size_t)k * GG + col];
                uint32_t hi = f2tf32(v);
                wbH[nt][kt][s2] = hi;
                wbL[nt][kt][s2] = f2tf32(v - __uint_as_float(hi));
            }
        }
    }

    float c_reg = 0.f;   // cell state (valid for tid < 64)

    for (int t = 0; t < TT; t++) {
        // prefetch xg gate preacts (independent of h_{t-1})
        float xr0, xr1, xr2, xr3;
        if (tid < 64) {
            const float* xp = &xg[((size_t)(gb * TT) + t) * GG + u0 + gu];
            xr0 = xp[0 * DD]; xr1 = xp[1 * DD];
            xr2 = xp[2 * DD]; xr3 = xp[3 * DD];
        }

        // stage h_{t-1} into padded shared (L2-coherent loads)
        if (t > 0) {
            const float4* src = (const float4*)(g_hbuf[(t + 1) & 1]);
#pragma unroll
            for (int i = 0; i < 8; i++) {
                int idx = tid + 256 * i;
                int r = idx >> 7, c = idx & 127;
                *(float4*)&h_s[r * HSP + c * 4] = __ldcg(&src[idx]);
            }
        }
        __syncthreads();

        // tensor-core partial matvec over this warp's k-slice
        if (t > 0) {
            float accHL[2][4], accLH[2][4], accHH[2][4];
#pragma unroll
            for (int nt = 0; nt < 2; nt++)
#pragma unroll
                for (int r = 0; r < 4; r++) {
                    accHL[nt][r] = 0.f; accLH[nt][r] = 0.f; accHH[nt][r] = 0.f;
                }

            const int kb = 64 * wid;
#pragma unroll
            for (int kt = 0; kt < 8; kt++) {
                float a0 = h_s[lq * HSP       + kb + 8 * kt + lr];
                float a1 = h_s[(lq + 8) * HSP + kb + 8 * kt + lr];
                float a2 = h_s[lq * HSP       + kb + 8 * kt + 4 + lr];
                float a3 = h_s[(lq + 8) * HSP + kb + 8 * kt + 4 + lr];
                uint32_t aH[4], aL[4];
                aH[0] = f2tf32(a0); aL[0] = f2tf32(a0 - __uint_as_float(aH[0]));
                aH[1] = f2tf32(a1); aL[1] = f2tf32(a1 - __uint_as_float(aH[1]));
                aH[2] = f2tf32(a2); aL[2] = f2tf32(a2 - __uint_as_float(aH[2]));
                aH[3] = f2tf32(a3); aL[3] = f2tf32(a3 - __uint_as_float(aH[3]));
#pragma unroll
                for (int nt = 0; nt < 2; nt++) {
                    mma_tf32(accHL[nt], aH, wbL[nt][kt]);
                    mma_tf32(accLH[nt], aL, wbH[nt][kt]);
                    mma_tf32(accHH[nt], aH, wbH[nt][kt]);
                }
            }

            // fold the 3 passes, write partials: c0,c1 -> (b=lq, n=2lr..),
            // c2,c3 -> (b=lq+8, ...)
#pragma unroll
            for (int nt = 0; nt < 2; nt++) {
                float c0 = accHL[nt][0] + accLH[nt][0] + accHH[nt][0];
                float c1 = accHL[nt][1] + accLH[nt][1] + accHH[nt][1];
                float c2 = accHL[nt][2] + accLH[nt][2] + accHH[nt][2];
                float c3 = accHL[nt][3] + accLH[nt][3] + accHH[nt][3];
                const int n0 = nt * 8 + 2 * lr;
                red[wid][n0    ][lq    ] = c0;
                red[wid][n0 + 1][lq    ] = c1;
                red[wid][n0    ][lq + 8] = c2;
                red[wid][n0 + 1][lq + 8] = c3;
            }
        }
        __syncthreads();

        // gates: cross-warp reduce + nonlinearities + state update
        if (tid < 64) {
            float ga[4] = {xr0, xr1, xr2, xr3};
            if (t > 0) {
#pragma unroll
                for (int g = 0; g < 4; g++) {
                    const int jj = g * 4 + gu;
                    float s = 0.f;
#pragma unroll
                    for (int wq = 0; wq < 8; wq++)
                        s += red[wq][jj][gb];
                    ga[g] += s;
                }
            }
            float i_ = sigm(ga[0]);
            float f_ = sigm(ga[1]);
            float o_ = sigm(ga[3]);
            float cg = tfast(ga[2]);
            c_reg = f_ * c_reg + i_ * cg;
            float h = o_ * tfast(c_reg);
            __stcg(&g_hbuf[t & 1][gb * DD + u0 + gu], h);
            g_hseq[((size_t)(gb * TT) + t) * DD + u0 + gu] = h;
        }
        __syncthreads();

        // grid barrier (R7/R9-proven single atomic, self-resetting)
        if (tid == 0) {
            __threadfence();
            unsigned gen = g_bargen;
            if (atomicAdd(&g_barcount, 1u) == (unsigned)(gridDim.x - 1)) {
                g_barcount = 0;
                __threadfence();
                g_bargen = gen + 1;
            } else {
                while (g_bargen == gen) { }
                __threadfence();
            }
        }
        __syncthreads();
    }
}

// ---------------------------------------------------------------------------
// LN1 + residual: out = LN(hin)*sc + bi + res      (one block per row)
// ---------------------------------------------------------------------------
__global__ void __launch_bounds__(256)
ln_add_kernel(const float* __restrict__ hin, const float* __restrict__ res,
              const float* __restrict__ sc, const float* __restrict__ bi,
              float* __restrict__ out)
{
    __shared__ float ws[8], wq[8];
    const int row = blockIdx.x;
    const int tid = threadIdx.x;

    float2 v = ((const float2*)(hin + (size_t)row * DD))[tid];
    float s = v.x + v.y;
    float q = v.x * v.x + v.y * v.y;
#pragma unroll
    for (int o = 16; o; o >>= 1) {
        s += __shfl_xor_sync(~0u, s, o);
        q += __shfl_xor_sync(~0u, q, o);
    }
    if ((tid & 31) == 0) { ws[tid >> 5] = s; wq[tid >> 5] = q; }
    __syncthreads();
    if (tid < 32) {
        float s2 = (tid < 8) ? ws[tid] : 0.f;
        float q2 = (tid < 8) ? wq[tid] : 0.f;
#pragma unroll
        for (int o = 4; o; o >>= 1) {
            s2 += __shfl_xor_sync(~0u, s2, o);
            q2 += __shfl_xor_sync(~0u, q2, o);
        }
        if (tid == 0) { ws[0] = s2; wq[0] = q2; }
    }
    __syncthreads();
    float mean = ws[0] * (1.f / (float)DD);
    float var  = wq[0] * (1.f / (float)DD) - mean * mean;
    float inv  = rsqrtf(var + EPS);

    float2 r  = ((const float2*)(res + (size_t)row * DD))[tid];
    float2 sv = ((const float2*)sc)[tid];
    float2 bv = ((const float2*)bi)[tid];
    float2 o2;
    o2.x = (v.x - mean) * inv * sv.x + bv.x + r.x;
    o2.y = (v.y - mean) * inv * sv.y + bv.y + r.y;
    ((float2*)(out + (size_t)row * DD))[tid] = o2;
}

// ---------------------------------------------------------------------------
// Final: out = LN(ao*gate + hp)*sc + bi            (one block per row)
// ---------------------------------------------------------------------------
__global__ void __launch_bounds__(256)
final_kernel(const float* __restrict__ ao, const float* __restrict__ gate,
             const float* __restrict__ hp, const float* __restrict__ sc,
             const float* __restrict__ bi, float* __restrict__ out)
{
    __shared__ float ws[8], wq[8];
    const int row = blockIdx.x;
    const int tid = threadIdx.x;

    float2 a = ((const float2*)(ao   + (size_t)row * DD))[tid];
    float2 g = ((const float2*)(gate + (size_t)row * DD))[tid];
    float2 h = ((const float2*)(hp   + (size_t)row * DD))[tid];
    float2 v;
    v.x = a.x * g.x + h.x;
    v.y = a.y * g.y + h.y;

    float s = v.x + v.y;
    float q = v.x * v.x + v.y * v.y;
#pragma unroll
    for (int o = 16; o; o >>= 1) {
        s += __shfl_xor_sync(~0u, s, o);
        q += __shfl_xor_sync(~0u, q, o);
    }
    if ((tid & 31) == 0) { ws[tid >> 5] = s; wq[tid >> 5] = q; }
    __syncthreads();
    if (tid < 32) {
        float s2 = (tid < 8) ? ws[tid] : 0.f;
        float q2 = (tid < 8) ? wq[tid] : 0.f;
#pragma unroll
        for (int o = 4; o; o >>= 1) {
            s2 += __shfl_xor_sync(~0u, s2, o);
            q2 += __shfl_xor_sync(~0u, q2, o);
        }
        if (tid == 0) { ws[0] = s2; wq[0] = q2; }
    }
    __syncthreads();
    float mean = ws[0] * (1.f / (float)DD);
    float var  = wq[0] * (1.f / (float)DD) - mean * mean;
    float inv  = rsqrtf(var + EPS);

    float2 sv = ((const float2*)sc)[tid];
    float2 bv = ((const float2*)bi)[tid];
    float2 o2;
    o2.x = (v.x - mean) * inv * sv.x + bv.x;
    o2.y = (v.y - mean) * inv * sv.y + bv.y;
    ((float2*)(out + (size_t)row * DD))[tid] = o2;
}

// ---------------------------------------------------------------------------
// Attention: grid (b=16, h=8, quarter=4), 256 threads.
// ---------------------------------------------------------------------------
__global__ void __launch_bounds__(256)
attn_kernel(const float* __restrict__ q, const float* __restrict__ k,
            const float* __restrict__ v, float* __restrict__ ctx)
{
    __shared__ float Kt[HD][TT];   // 16 KB
    __shared__ float Vt[HD][TT];   // 16 KB

    const int b    = blockIdx.x;
    const int hh   = blockIdx.y;
    const int tid  = threadIdx.x;
    const int lane = tid & 31;
    const int wid  = tid >> 5;
    const float scale = 0.35355339059327373f;   // 1/sqrt(8)

    for (int idx = tid; idx < TT * HD; idx += 256) {
        int s = idx >> 3, d = idx & 7;
        size_t off = ((size_t)(b * TT) + s) * QKVD + hh * HD + d;
        Kt[d][s] = k[off];
        Vt[d][s] = v[off];
    }
    __syncthreads();

    const int row0 = blockIdx.z * 128 + wid * 16;
    for (int r = 0; r < 16; r++) {
        const int qrow = row0 + r;
        const float* qp = &q[((size_t)(b * TT) + qrow) * QKVD + hh * HD];
        float4 q0 = *(const float4*)qp;
        float4 q1 = *(const float4*)(qp + 4);
        float qv[8];
        qv[0] = q0.x * scale; qv[1] = q0.y * scale;
        qv[2] = q0.z * scale; qv[3] = q0.w * scale;
        qv[4] = q1.x * scale; qv[5] = q1.y * scale;
        qv[6] = q1.z * scale; qv[7] = q1.w * scale;

        float sc[16];
#pragma unroll
        for (int kk = 0; kk < 16; kk++) {
            int s = kk * 32 + lane;
            float acc = 0.f;
#pragma unroll
            for (int d = 0; d < 8; d++) acc += qv[d] * Kt[d][s];
            sc[kk] = acc;
        }
        float m = sc[0];
#pragma unroll
        for (int kk = 1; kk < 16; kk++) m = fmaxf(m, sc[kk]);
#pragma unroll
        for (int o = 16; o; o >>= 1)
            m = fmaxf(m, __shfl_xor_sync(~0u, m, o));
        float sum = 0.f;
#pragma unroll
        for (int kk = 0; kk < 16; kk++) {
            sc[kk] = __expf(sc[kk] - m);
            sum += sc[kk];
        }
#pragma unroll
        for (int o = 16; o; o >>= 1)
            sum += __shfl_xor_sync(~0u, sum, o);

        float acc[8];
#pragma unroll
        for (int d = 0; d < 8; d++) acc[d] = 0.f;
#pragma unroll
        for (int kk = 0; kk < 16; kk++) {
            int s = kk * 32 + lane;
            float wgt = sc[kk];
#pragma unroll
            for (int d = 0; d < 8; d++) acc[d] += wgt * Vt[d][s];
        }
#pragma unroll
        for (int d = 0; d < 8; d++)
#pragma unroll
            for (int o = 16; o; o >>= 1)
                acc[d] += __shfl_xor_sync(~0u, acc[d], o);

        if (lane == 0) {
            float invs = 1.f / sum;
            float* op = &ctx[((size_t)(b * TT) + qrow) * QKVD + hh * HD];
            float4 o0 = {acc[0] * invs, acc[1] * invs, acc[2] * invs, acc[3] * invs};
            float4 o1 = {acc[4] * invs, acc[5] * invs, acc[6] * invs, acc[7] * invs};
            *(float4*)op       = o0;
            *(float4*)(op + 4) = o1;
        }
    }
}

// ---------------------------------------------------------------------------
// Launch
// ---------------------------------------------------------------------------
extern "C" void kernel_launch(void* const* d_in, const int* in_sizes, int n_in,
                              void* d_out, int out_size)
{
    (void)in_sizes; (void)n_in; (void)out_size;

    const float* x   = (const float*)d_in[0];
    const float* Wx  = (const float*)d_in[1];
    const float* Wh  = (const float*)d_in[2];
    const float* b   = (const float*)d_in[3];
    const float* l1s = (const float*)d_in[4];
    const float* l1b = (const float*)d_in[5];
    const float* Wq  = (const float*)d_in[6];
    const float* bq  = (const float*)d_in[7];
    const float* Wk  = (const float*)d_in[8];
    const float* bk  = (const float*)d_in[9];
    const float* Wv  = (const float*)d_in[10];
    const float* bv  = (const float*)d_in[11];
    const float* Wo  = (const float*)d_in[12];
    const float* bo  = (const float*)d_in[13];
    const float* Wg  = (const float*)d_in[14];
    const float* bg  = (const float*)d_in[15];
    const float* l2s = (const float*)d_in[16];
    const float* l2b = (const float*)d_in[17];
    float* out = (float*)d_out;

    float *xg, *hseq, *hp, *qb, *kb, *vb, *ctx, *ao, *gate;
    cudaGetSymbolAddress((void**)&xg,   g_xg);
    cudaGetSymbolAddress((void**)&hseq, g_hseq);
    cudaGetSymbolAddress((void**)&hp,   g_hp);
    cudaGetSymbolAddress((void**)&qb,   g_q);
    cudaGetSymbolAddress((void**)&kb,   g_k);
    cudaGetSymbolAddress((void**)&vb,   g_v);
    cudaGetSymbolAddress((void**)&ctx,  g_ctx);
    cudaGetSymbolAddress((void**)&ao,   g_ao);
    cudaGetSymbolAddress((void**)&gate, g_gate);

    // 1. xg = x @ Wx + b    [8192,2048] = [8192,512]@[512,2048]  (3xTF32 MMA)
    gemm_tf32_kernel<0><<<dim3(GG / 128, NROW / 128), 256>>>(x, Wx, b, xg, DD, GG);

    // 2. LSTM recurrence (persistent, tensor-core matvec, atomic grid barrier)
    lstm_kernel<<<128, 256>>>(xg, Wh);

    // 3. hp = LN1(hseq) + x
    ln_add_kernel<<<NROW, 256>>>(hseq, x, l1s, l1b, hp);

    // 4. fused q,k,v projections   [8192,64] = [8192,512]@[512,64]
    qkv_kernel<<<dim3(1, NROW / 64, 3), 256>>>(
        hp, Wq, bq, Wk, bk, Wv, bv, qb, kb, vb);

    // 5. attention -> ctx
    attn_kernel<<<dim3(BB, NH, 4), 256>>>(qb, kb, vb, ctx);

    // 6. attn_out = ctx @ Wo + bo     [8192,512] = [8192,64]@[64,512]
    gemm2_kernel<128, 128, 16, 8, 8, 0><<<dim3(DD / 128, NROW / 128), 256>>>(
        ctx, Wo, bo, ao, QKVD, DD);

    // 7. gate = sigmoid(hp @ Wg + bg) [8192,512] = [8192,512]@[512,512]  (3xTF32)
    gemm_tf32_kernel<1><<<dim3(DD / 128, NROW / 128), 256>>>(hp, Wg, bg, gate, DD, DD);

    // 8. out = LN2(ao*gate + hp)
    final_kernel<<<NROW, 256>>>(ao, gate, hp, l2s, l2b, out);
}